// round 17
// baseline (speedup 1.0000x reference)
#include <cuda_runtime.h>
#include <cuda_fp16.h>
#include <cstdint>

typedef unsigned int u32;

#define N_HEADS 16
#define NPG   64
#define IN_F  128
#define OUT_F 128

#define WK_WORDS (IN_F * 64)   // fp16 W image per head: 8192 u32 = 32 KB
#define XT_WORDS (NPG * 64)    // fp16 X image: 4096 u32 = 16 KB
#define SMEM_BYTES ((WK_WORDS + XT_WORDS) * 4)   // 49152

// grid-shared scratch: prebuilt fp16 swizzled W images + ready flags
__device__ u32 g_wimg[N_HEADS * WK_WORDS];   // 512 KB
__device__ int g_flag[N_HEADS];

__device__ __forceinline__ u32 pack_h2(float lo, float hi) {
    __half2 h = __floats2half2_rn(lo, hi);
    return *(u32*)&h;
}
__device__ __forceinline__ u32 smem_addr(const void* p) {
    return (u32)__cvta_generic_to_shared(p);
}

#define CP_ASYNC16(dst, src) \
    asm volatile("cp.async.cg.shared.global [%0], [%1], 16;" :: "r"(dst), "l"(src))
#define CP_COMMIT() asm volatile("cp.async.commit_group;" ::: "memory")
#define CP_WAIT0()  asm volatile("cp.async.wait_group 0;" ::: "memory")

#define LDSM_X4(r0, r1, r2, r3, a) \
    asm volatile("ldmatrix.sync.aligned.m8n8.x4.shared.b16 {%0,%1,%2,%3}, [%4];" \
        : "=r"(r0), "=r"(r1), "=r"(r2), "=r"(r3) : "r"(a))
#define LDSM_X4_T(r0, r1, r2, r3, a) \
    asm volatile("ldmatrix.sync.aligned.m8n8.x4.trans.shared.b16 {%0,%1,%2,%3}, [%4];" \
        : "=r"(r0), "=r"(r1), "=r"(r2), "=r"(r3) : "r"(a))

__device__ __forceinline__ void mma_f16(float* c, u32 a0, u32 a1, u32 a2, u32 a3,
                                        u32 b0, u32 b1)
{
    asm volatile(
        "mma.sync.aligned.m16n8k16.row.col.f32.f16.f16.f32 "
        "{%0,%1,%2,%3}, {%4,%5,%6,%7}, {%8,%9}, {%0,%1,%2,%3};"
        : "+f"(c[0]), "+f"(c[1]), "+f"(c[2]), "+f"(c[3])
        : "r"(a0), "r"(a1), "r"(a2), "r"(a3), "r"(b0), "r"(b1));
}

__global__ void __launch_bounds__(256, 2)
mhl_mma_kernel(const float* __restrict__ x,
               const int*   __restrict__ head,
               const float* __restrict__ kern,
               const float* __restrict__ bias,
               float*       __restrict__ out)
{
    extern __shared__ u32 smem[];
    u32* Wk = smem;               // [128 k][64 w] fp16, chunk-swizzled (verbatim image copy)
    u32* XT = smem + WK_WORDS;    // [64 node][64 w] fp16, chunk-swizzled

    const int tid  = threadIdx.x;
    const int wid  = tid >> 5;             // 8 warps: 2m x 4n
    const int lane = tid & 31;
    const int gid  = lane >> 2;
    const int tig  = lane & 3;
    const int g    = blockIdx.x;
    const int h    = __ldg(head + g);

    const int m0 = (wid >> 2) * 32;        // 0, 32
    const int n0 = (wid & 3) * 32;         // 0, 32, 64, 96

    // ---- builders: CTAs 0..15 create the fp16 swizzled image for head = blockIdx.x ----
    if (g < N_HEADS) {
        const float* W = kern + (size_t)g * IN_F * OUT_F;
        u32* img = g_wimg + (size_t)g * WK_WORDS;
        #pragma unroll
        for (int it = 0; it < 8; it++) {
            const int idx = tid + it * 256;        // 2048 chunks
            const int k   = idx >> 4;
            const int nc  = idx & 15;
            const float4* src = (const float4*)(W + k * OUT_F + nc * 8);
            float4 v0 = src[0], v1 = src[1];
            uint4 o;
            o.x = pack_h2(v0.x, v0.y);
            o.y = pack_h2(v0.z, v0.w);
            o.z = pack_h2(v1.x, v1.y);
            o.w = pack_h2(v1.z, v1.w);
            *(uint4*)&img[k * 64 + ((nc ^ (k & 7)) << 2)] = o;
        }
        __syncthreads();
        if (tid == 0) {
            __threadfence();
            atomicExch(&g_flag[g], 1);     // release
        }
    }

    // ---- X stage (overlaps builders / the wait): LDG.128 -> fp16 -> swizzled STS.128 ----
    {
        const float4* X4 = (const float4*)(x + (size_t)g * NPG * IN_F);
        #pragma unroll
        for (int it = 0; it < 4; it++) {
            const int idx  = tid + it * 256;       // 1024 chunks
            const int node = idx >> 4;
            const int kc   = idx & 15;
            float4 v0 = X4[node * 32 + kc * 2];
            float4 v1 = X4[node * 32 + kc * 2 + 1];
            uint4 o;
            o.x = pack_h2(v0.x, v0.y);
            o.y = pack_h2(v0.z, v0.w);
            o.z = pack_h2(v1.x, v1.y);
            o.w = pack_h2(v1.z, v1.w);
            *(uint4*)&XT[node * 64 + ((kc ^ (node & 7)) << 2)] = o;
        }
    }

    // ---- wait for our head's image (acquire), then 32 KB linear cp.async copy ----
    if (tid == 0) {
        int r;
        do {
            asm volatile("ld.acquire.gpu.global.b32 %0, [%1];"
                         : "=r"(r) : "l"(&g_flag[h]) : "memory");
        } while (r == 0);
    }
    __syncthreads();
    {
        const u32* src = g_wimg + (size_t)h * WK_WORDS;
        const u32 dstb = smem_addr(Wk);
        #pragma unroll
        for (int i = 0; i < 8; i++) {
            const int idx = tid + i * 256;         // 2048 x 16B
            CP_ASYNC16(dstb + (u32)idx * 16u, src + idx * 4);
        }
        CP_COMMIT();
        CP_WAIT0();
    }
    __syncthreads();

    float acc[2][4][4];
    #pragma unroll
    for (int i = 0; i < 2; i++)
        #pragma unroll
        for (int j = 0; j < 4; j++)
            #pragma unroll
            for (int r = 0; r < 4; r++)
                acc[i][j][r] = 0.0f;

    // A (non-trans LDSM): rows = m, chunks along k
    const int arow0 = m0 + (lane & 7) + 8 * ((lane >> 3) & 1);
    const int akc   = (lane >> 4) & 1;
    const u32 abase0 = smem_addr(&XT[arow0 * 64]);
    const u32 abase1 = smem_addr(&XT[(arow0 + 16) * 64]);
    const int ae0 = arow0 & 7, ae1 = (arow0 + 16) & 7;

    // B (trans LDSM): rows = k, chunks along n
    const int brow_off = (lane & 7) + 8 * ((lane >> 3) & 1);
    const int bnc_off  = (lane >> 4) & 1;

    #pragma unroll
    for (int s = 0; s < 8; s++) {
        u32 a0[4], a1[4];
        LDSM_X4(a0[0], a0[1], a0[2], a0[3], abase0 + ((((2 * s) + akc) ^ ae0) << 4));
        LDSM_X4(a1[0], a1[1], a1[2], a1[3], abase1 + ((((2 * s) + akc) ^ ae1) << 4));
        const int krow = 16 * s + brow_off;
        const u32 bstride = smem_addr(&Wk[krow * 64]);
        u32 b[2][4];
        #pragma unroll
        for (int p = 0; p < 2; p++) {
            const int nc = (n0 >> 3) + 2 * p + bnc_off;
            LDSM_X4_T(b[p][0], b[p][1], b[p][2], b[p][3],
                      bstride + ((nc ^ (krow & 7)) << 4));
        }
        #pragma unroll
        for (int j = 0; j < 4; j++) {
            const int p = j >> 1, q = j & 1;
            mma_f16(acc[0][j], a0[0], a0[1], a0[2], a0[3], b[p][2 * q], b[p][2 * q + 1]);
            mma_f16(acc[1][j], a1[0], a1[1], a1[2], a1[3], b[p][2 * q], b[p][2 * q + 1]);
        }
    }

    // ---- epilogue: bias + coalesced float2 stores ----
    float bb[4][2];
    #pragma unroll
    for (int j = 0; j < 4; j++) {
        const int col = n0 + 8 * j + 2 * tig;
        bb[j][0] = __ldg(bias + (size_t)h * OUT_F + col);
        bb[j][1] = __ldg(bias + (size_t)h * OUT_F + col + 1);
    }

    #pragma unroll
    for (int i = 0; i < 2; i++) {
        const int node0 = g * NPG + m0 + 16 * i + gid;
        #pragma unroll
        for (int j = 0; j < 4; j++) {
            const int col = n0 + 8 * j + 2 * tig;
            float2 v0 = make_float2(acc[i][j][0] + bb[j][0], acc[i][j][1] + bb[j][1]);
            float2 v1 = make_float2(acc[i][j][2] + bb[j][0], acc[i][j][3] + bb[j][1]);
            *(float2*)&out[(size_t)node0 * OUT_F + col]       = v0;
            *(float2*)&out[(size_t)(node0 + 8) * OUT_F + col] = v1;
        }
    }
}

extern "C" void kernel_launch(void* const* d_in, const int* in_sizes, int n_in,
                              void* d_out, int out_size)
{
    const float* inputs = (const float*)d_in[0];
    const int*   head   = (const int*)d_in[2];
    const float* kern   = (const float*)d_in[3];
    const float* bias   = (const float*)d_in[4];
    float*       out    = (float*)d_out;
    const int n_graphs  = in_sizes[2];   // 256

    static void* flag_addr = nullptr;
    static bool attr_set = false;
    if (!attr_set) {
        cudaFuncSetAttribute(mhl_mma_kernel, cudaFuncAttributeMaxDynamicSharedMemorySize, SMEM_BYTES);
        cudaGetSymbolAddress(&flag_addr, g_flag);
        attr_set = true;
    }

    cudaMemsetAsync(flag_addr, 0, N_HEADS * sizeof(int));
    mhl_mma_kernel<<<n_graphs, 256, SMEM_BYTES>>>(inputs, head, kern, bias, out);
}